// round 2
// baseline (speedup 1.0000x reference)
#include <cuda_runtime.h>
#include <cuda_bf16.h>

// Problem shapes (fixed by reference):
//   node_emb      [100000, 64] f32
//   hyperedge_emb [ 50000, 64] f32
//   h             [200000]      i32   (JAX w/o x64 downgrades int64 -> int32)
//   X             [200000, 8]   i32
//   out           [200000, 2]   f32
//
// Layout: 8 lanes per candidate (each lane owns an 8-dim slice),
// 4 candidates per warp, 256 threads/block -> 32 candidates/block.

#define SET_SIZE 8
#define EMB_DIM  64
#define N_NODES_MAX 100000
#define N_HYPER_MAX 50000

__device__ __forceinline__ float dot8(const float4& a0, const float4& a1,
                                      const float4& b0, const float4& b1) {
    return a0.x * b0.x + a0.y * b0.y + a0.z * b0.z + a0.w * b0.w +
           a1.x * b1.x + a1.y * b1.y + a1.z * b1.z + a1.w * b1.w;
}

__device__ __forceinline__ float fast_sigmoid(float x) {
    return 1.0f / (1.0f + __expf(-x));
}

__device__ __forceinline__ int clampi(int v, int hi) {
    return min(max(v, 0), hi);
}

__global__ __launch_bounds__(256, 1)
void hyperedge_score_kernel(const float* __restrict__ node_emb,
                            const float* __restrict__ hyper_emb,
                            const int* __restrict__ h,
                            const int* __restrict__ X,
                            float* __restrict__ out,
                            int n_cand, int n_nodes, int n_hyper)
{
    const int lane = threadIdx.x & 31;
    const int warp = threadIdx.x >> 5;
    const int seg  = lane >> 3;   // candidate within warp (0..3)
    const int sub  = lane & 7;    // 8-dim slice id      (0..7)

    int e = (blockIdx.x * 8 + warp) * 4 + seg;
    const bool valid = (e < n_cand);
    int ec = valid ? e : (n_cand - 1);   // 200000 % 32 == 0, but stay safe

    // ---- coalesced index loads ----
    // X: the 32 lanes of a warp read 32 consecutive int32 (one 128B sector).
    int my_idx = clampi(X[ec * SET_SIZE + sub], n_nodes - 1);
    int h_idx  = clampi(h[ec], n_hyper - 1);

    // ---- gather src slice (dims [sub*8, sub*8+8)) ----
    const float4* sp = reinterpret_cast<const float4*>(
        hyper_emb + (long long)h_idx * EMB_DIM + sub * 8);
    float4 s0 = __ldg(sp);
    float4 s1 = __ldg(sp + 1);

    // ---- gather the 8 node-embedding slices (issue all loads up front) ----
    float4 n0[SET_SIZE], n1[SET_SIZE];
    #pragma unroll
    for (int t = 0; t < SET_SIZE; t++) {
        int idx = __shfl_sync(0xffffffffu, my_idx, seg * 8 + t);
        const float4* np = reinterpret_cast<const float4*>(
            node_emb + (long long)idx * EMB_DIM + sub * 8);
        n0[t] = __ldg(np);
        n1[t] = __ldg(np + 1);
    }

    // ---- per-lane partial dot products ----
    // acc[0..7]   : star  <src, node_t>
    // acc[8..43]  : pairs <node_a, node_b>, a <= b  (36 incl. diagonal)
    float acc[44];
    #pragma unroll
    for (int t = 0; t < SET_SIZE; t++)
        acc[t] = dot8(s0, s1, n0[t], n1[t]);

    {
        int k = 8;
        #pragma unroll
        for (int a = 0; a < SET_SIZE; a++) {
            #pragma unroll
            for (int b = a; b < SET_SIZE; b++) {
                acc[k++] = dot8(n0[a], n1[a], n0[b], n1[b]);
            }
        }
    }

    // ---- reduce each of the 44 partials across the 8-lane segment ----
    // xor masks 1,2,4 stay within the aligned 8-lane group; all 4 segments
    // of the warp reduce simultaneously in the same instructions.
    #pragma unroll
    for (int i = 0; i < 44; i++) {
        acc[i] += __shfl_xor_sync(0xffffffffu, acc[i], 1);
        acc[i] += __shfl_xor_sync(0xffffffffu, acc[i], 2);
        acc[i] += __shfl_xor_sync(0xffffffffu, acc[i], 4);
    }

    // ---- mins (sigmoid is monotone: min(sigmoid(x)) == sigmoid(min(x))) ----
    float star = acc[0];
    #pragma unroll
    for (int i = 1; i < SET_SIZE; i++) star = fminf(star, acc[i]);

    float clique = acc[8];
    #pragma unroll
    for (int i = 9; i < 44; i++) clique = fminf(clique, acc[i]);

    if (valid && sub == 0) {
        float2 o = make_float2(fast_sigmoid(star), fast_sigmoid(clique));
        reinterpret_cast<float2*>(out)[e] = o;
    }
}

extern "C" void kernel_launch(void* const* d_in, const int* in_sizes, int n_in,
                              void* d_out, int out_size) {
    const float* node_emb  = (const float*)d_in[0];
    const float* hyper_emb = (const float*)d_in[1];
    const int*   h         = (const int*)d_in[2];
    const int*   X         = (const int*)d_in[3];
    float*       out       = (float*)d_out;

    const int n_cand  = in_sizes[2];                 // length of h == N_CAND
    const int n_nodes = in_sizes[0] / EMB_DIM;       // rows of node_emb
    const int n_hyper = in_sizes[1] / EMB_DIM;       // rows of hyperedge_emb

    const int cands_per_block = 32;                  // 8 warps * 4 candidates
    const int blocks = (n_cand + cands_per_block - 1) / cands_per_block;

    hyperedge_score_kernel<<<blocks, 256>>>(node_emb, hyper_emb, h, X, out,
                                            n_cand, n_nodes, n_hyper);
}

// round 3
// speedup vs baseline: 1.8078x; 1.8078x over previous
#include <cuda_runtime.h>
#include <cuda_bf16.h>

// Problem shapes (fixed by reference):
//   node_emb      [100000, 64] f32
//   hyperedge_emb [ 50000, 64] f32
//   h             [200000]      i32
//   X             [200000, 8]   i32
//   out           [200000, 2]   f32
//
// Layout: 8 lanes per candidate, 4 candidates per warp, 256 threads/block.
// Each lane owns a NON-contiguous 8-dim slice: dims [4*sub,4*sub+4) and
// [32+4*sub, 32+4*sub+4). This makes each segment's two LDG.128s cover
// exactly one 128B line each (bytes [0,128) and [128,256) of the row),
// halving L1tex wavefronts vs a contiguous slice.

#define SET_SIZE 8
#define EMB_DIM  64

__device__ __forceinline__ float dot8(const float4& a0, const float4& a1,
                                      const float4& b0, const float4& b1) {
    return a0.x * b0.x + a0.y * b0.y + a0.z * b0.z + a0.w * b0.w +
           a1.x * b1.x + a1.y * b1.y + a1.z * b1.z + a1.w * b1.w;
}

__device__ __forceinline__ float fast_sigmoid(float x) {
    return 1.0f / (1.0f + __expf(-x));
}

__device__ __forceinline__ int clampi(int v, int hi) {
    return min(max(v, 0), hi);
}

__global__ __launch_bounds__(256, 2)
void hyperedge_score_kernel(const float* __restrict__ node_emb,
                            const float* __restrict__ hyper_emb,
                            const int* __restrict__ h,
                            const int* __restrict__ X,
                            float* __restrict__ out,
                            int n_cand, int n_nodes, int n_hyper)
{
    const int lane = threadIdx.x & 31;
    const int warp = threadIdx.x >> 5;
    const int seg  = lane >> 3;   // candidate within warp (0..3)
    const int sub  = lane & 7;    // slice id             (0..7)

    int e = (blockIdx.x * 8 + warp) * 4 + seg;
    const bool valid = (e < n_cand);
    int ec = valid ? e : (n_cand - 1);   // 200000 % 32 == 0, but stay safe

    // ---- coalesced index loads (one 128B line per warp for X) ----
    int my_idx = clampi(X[ec * SET_SIZE + sub], n_nodes - 1);
    int h_idx  = clampi(h[ec], n_hyper - 1);

    // Slice offsets (in floats): first half of row + second half of row.
    const int o0 = sub * 4;        // dims [4sub, 4sub+4)   -> bytes [0,128) per segment
    const int o1 = 32 + sub * 4;   // dims [32+4sub, ..+4)  -> bytes [128,256)

    // ---- gather src slice ----
    const float* srow = hyper_emb + (long long)h_idx * EMB_DIM;
    float4 s0 = __ldg(reinterpret_cast<const float4*>(srow + o0));
    float4 s1 = __ldg(reinterpret_cast<const float4*>(srow + o1));

    // ---- gather the 8 node-embedding slices (issue all loads up front) ----
    float4 n0[SET_SIZE], n1[SET_SIZE];
    #pragma unroll
    for (int t = 0; t < SET_SIZE; t++) {
        int idx = __shfl_sync(0xffffffffu, my_idx, seg * 8 + t);
        const float* nrow = node_emb + (long long)idx * EMB_DIM;
        n0[t] = __ldg(reinterpret_cast<const float4*>(nrow + o0));
        n1[t] = __ldg(reinterpret_cast<const float4*>(nrow + o1));
    }

    // ---- per-lane partial dot products ----
    // acc[0..7]   : star  <src, node_t>
    // acc[8..43]  : pairs <node_a, node_b>, a <= b  (36 incl. diagonal)
    float acc[44];
    #pragma unroll
    for (int t = 0; t < SET_SIZE; t++)
        acc[t] = dot8(s0, s1, n0[t], n1[t]);

    {
        int k = 8;
        #pragma unroll
        for (int a = 0; a < SET_SIZE; a++) {
            #pragma unroll
            for (int b = a; b < SET_SIZE; b++) {
                acc[k++] = dot8(n0[a], n1[a], n0[b], n1[b]);
            }
        }
    }

    // ---- reduce each of the 44 partials across the 8-lane segment ----
    #pragma unroll
    for (int i = 0; i < 44; i++) {
        acc[i] += __shfl_xor_sync(0xffffffffu, acc[i], 1);
        acc[i] += __shfl_xor_sync(0xffffffffu, acc[i], 2);
        acc[i] += __shfl_xor_sync(0xffffffffu, acc[i], 4);
    }

    // ---- mins (sigmoid is monotone: min(sigmoid(x)) == sigmoid(min(x))) ----
    float star = acc[0];
    #pragma unroll
    for (int i = 1; i < SET_SIZE; i++) star = fminf(star, acc[i]);

    float clique = acc[8];
    #pragma unroll
    for (int i = 9; i < 44; i++) clique = fminf(clique, acc[i]);

    if (valid && sub == 0) {
        float2 o = make_float2(fast_sigmoid(star), fast_sigmoid(clique));
        reinterpret_cast<float2*>(out)[e] = o;
    }
}

extern "C" void kernel_launch(void* const* d_in, const int* in_sizes, int n_in,
                              void* d_out, int out_size) {
    const float* node_emb  = (const float*)d_in[0];
    const float* hyper_emb = (const float*)d_in[1];
    const int*   h         = (const int*)d_in[2];
    const int*   X         = (const int*)d_in[3];
    float*       out       = (float*)d_out;

    const int n_cand  = in_sizes[2];
    const int n_nodes = in_sizes[0] / EMB_DIM;
    const int n_hyper = in_sizes[1] / EMB_DIM;

    const int cands_per_block = 32;   // 8 warps * 4 candidates
    const int blocks = (n_cand + cands_per_block - 1) / cands_per_block;

    hyperedge_score_kernel<<<blocks, 256>>>(node_emb, hyper_emb, h, X, out,
                                            n_cand, n_nodes, n_hyper);
}

// round 4
// speedup vs baseline: 1.8570x; 1.0272x over previous
#include <cuda_runtime.h>
#include <cuda_bf16.h>

// Problem shapes:
//   node_emb      [100000, 64] f32
//   hyperedge_emb [ 50000, 64] f32
//   h             [200000]      i32
//   X             [200000, 8]   i32
//   out           [200000, 2]   f32
//
// Layout: 16 lanes per candidate (lane owns one float4 = 4 dims),
// 2 candidates per warp, 128 threads/block -> 8 candidates/block.
// Cross-lane sums use a recursive-halving reduce-scatter (15 shuffles per
// 16-value group) instead of per-value butterfly all-reduce; the induced
// bit-reversal permutation is harmless because every group feeds a min.

#define SET_SIZE 8
#define EMB_DIM  64
#define FULL 0xffffffffu
#define PAD_BIG 1e30f

__device__ __forceinline__ float dot4(const float4& a, const float4& b) {
    return a.x * b.x + a.y * b.y + a.z * b.z + a.w * b.w;
}

__device__ __forceinline__ float fast_sigmoid(float x) {
    return 1.0f / (1.0f + __expf(-x));
}

__device__ __forceinline__ int clampi(int v, int hi) {
    return min(max(v, 0), hi);
}

// Reduce-scatter 16 values across the 16-lane segment (sub = lane & 15).
// Afterwards each lane holds the full 16-lane sum of value index bitrev4(sub).
__device__ __forceinline__ float rs16(float (&cur)[16], int sub) {
    // stage m=1 (8 live values)
    #pragma unroll
    for (int j = 0; j < 8; j++) {
        float send = (sub & 1) ? cur[j] : cur[j + 8];
        float keep = (sub & 1) ? cur[j + 8] : cur[j];
        cur[j] = keep + __shfl_xor_sync(FULL, send, 1);
    }
    // stage m=2 (4 live)
    #pragma unroll
    for (int j = 0; j < 4; j++) {
        float send = (sub & 2) ? cur[j] : cur[j + 4];
        float keep = (sub & 2) ? cur[j + 4] : cur[j];
        cur[j] = keep + __shfl_xor_sync(FULL, send, 2);
    }
    // stage m=4 (2 live)
    #pragma unroll
    for (int j = 0; j < 2; j++) {
        float send = (sub & 4) ? cur[j] : cur[j + 2];
        float keep = (sub & 4) ? cur[j + 2] : cur[j];
        cur[j] = keep + __shfl_xor_sync(FULL, send, 4);
    }
    // stage m=8 (1 live)
    {
        float send = (sub & 8) ? cur[0] : cur[1];
        float keep = (sub & 8) ? cur[1] : cur[0];
        cur[0] = keep + __shfl_xor_sync(FULL, send, 8);
    }
    return cur[0];
}

__global__ __launch_bounds__(128, 7)
void hyperedge_score_kernel(const float* __restrict__ node_emb,
                            const float* __restrict__ hyper_emb,
                            const int* __restrict__ h,
                            const int* __restrict__ X,
                            float* __restrict__ out,
                            int n_cand, int n_nodes, int n_hyper)
{
    const int lane = threadIdx.x & 31;
    const int warp = threadIdx.x >> 5;
    const int seg  = lane >> 4;   // candidate within warp (0..1)
    const int sub  = lane & 15;   // float4 slice id      (0..15)

    int e = (blockIdx.x * 4 + warp) * 2 + seg;
    const bool valid = (e < n_cand);
    int ec = valid ? e : (n_cand - 1);

    // Index loads (lanes 0..7 and 8..15 of a segment read the same 8 ints).
    int my_idx = clampi(X[ec * SET_SIZE + (sub & 7)], n_nodes - 1);
    int h_idx  = clampi(h[ec], n_hyper - 1);

    // Gather src slice: one float4 (dims [4*sub, 4*sub+4)).
    float4 s = __ldg(reinterpret_cast<const float4*>(
        hyper_emb + (long long)h_idx * EMB_DIM + sub * 4));

    // Gather 8 node slices, all loads issued up front (MLP).
    float4 nv[SET_SIZE];
    #pragma unroll
    for (int t = 0; t < SET_SIZE; t++) {
        int idx = __shfl_sync(FULL, my_idx, seg * 16 + t);
        nv[t] = __ldg(reinterpret_cast<const float4*>(
            node_emb + (long long)idx * EMB_DIM + sub * 4));
    }

    float cur[16];

    // ---- group 0: star (indices 0..7) + diagonal (indices 8..15) ----
    #pragma unroll
    for (int t = 0; t < SET_SIZE; t++) cur[t] = dot4(s, nv[t]);
    #pragma unroll
    for (int t = 0; t < SET_SIZE; t++) cur[8 + t] = dot4(nv[t], nv[t]);

    float v = rs16(cur, sub);
    // bitrev: even lanes hold star sums, odd lanes hold diagonal sums.
    // Min within each parity class (masks 2,4,8 preserve parity).
    v = fminf(v, __shfl_xor_sync(FULL, v, 2));
    v = fminf(v, __shfl_xor_sync(FULL, v, 4));
    v = fminf(v, __shfl_xor_sync(FULL, v, 8));
    float star_min = v;                               // valid on even lanes
    float diag_min = __shfl_xor_sync(FULL, v, 1);     // odd lanes' min, now on even

    // ---- off-diagonal pairs: 28 dots in 2 chunks of 16 ----
    // chunk 0: (0,1..7) (1,2..7) (2,3..5)  -> 16 pairs
    {
        const int PA0[16] = {0,0,0,0,0,0,0, 1,1,1,1,1,1, 2,2,2};
        const int PB0[16] = {1,2,3,4,5,6,7, 2,3,4,5,6,7, 3,4,5};
        #pragma unroll
        for (int k = 0; k < 16; k++) cur[k] = dot4(nv[PA0[k]], nv[PB0[k]]);
    }
    float p0 = rs16(cur, sub);

    // chunk 1: (2,6)(2,7) (3,4..7) (4,5..7) (5,6)(5,7) (6,7) -> 12 pairs + 4 pads
    {
        const int PA1[12] = {2,2, 3,3,3,3, 4,4,4, 5,5, 6};
        const int PB1[12] = {6,7, 4,5,6,7, 5,6,7, 6,7, 7};
        #pragma unroll
        for (int k = 0; k < 12; k++) cur[k] = dot4(nv[PA1[k]], nv[PB1[k]]);
        #pragma unroll
        for (int k = 12; k < 16; k++) cur[k] = PAD_BIG;
    }
    float p1 = rs16(cur, sub);

    float pmin = fminf(p0, p1);
    pmin = fminf(pmin, __shfl_xor_sync(FULL, pmin, 1));
    pmin = fminf(pmin, __shfl_xor_sync(FULL, pmin, 2));
    pmin = fminf(pmin, __shfl_xor_sync(FULL, pmin, 4));
    pmin = fminf(pmin, __shfl_xor_sync(FULL, pmin, 8));

    if (valid && sub == 0) {
        float clique = fminf(diag_min, pmin);
        float2 o = make_float2(fast_sigmoid(star_min), fast_sigmoid(clique));
        reinterpret_cast<float2*>(out)[e] = o;
    }
}

extern "C" void kernel_launch(void* const* d_in, const int* in_sizes, int n_in,
                              void* d_out, int out_size) {
    const float* node_emb  = (const float*)d_in[0];
    const float* hyper_emb = (const float*)d_in[1];
    const int*   h         = (const int*)d_in[2];
    const int*   X         = (const int*)d_in[3];
    float*       out       = (float*)d_out;

    const int n_cand  = in_sizes[2];
    const int n_nodes = in_sizes[0] / EMB_DIM;
    const int n_hyper = in_sizes[1] / EMB_DIM;

    const int cands_per_block = 8;    // 4 warps * 2 candidates
    const int blocks = (n_cand + cands_per_block - 1) / cands_per_block;

    hyperedge_score_kernel<<<blocks, 128>>>(node_emb, hyper_emb, h, X, out,
                                            n_cand, n_nodes, n_hyper);
}

// round 5
// speedup vs baseline: 1.9248x; 1.0365x over previous
#include <cuda_runtime.h>
#include <cuda_bf16.h>

// Problem shapes:
//   node_emb      [100000, 64] f32
//   hyperedge_emb [ 50000, 64] f32
//   h             [200000]      i32
//   X             [200000, 8]   i32
//   out           [200000, 2]   f32
//
// Layout: 16 lanes per candidate (lane owns one float4 = 4 dims),
// 2 candidates per warp, 128 threads/block -> 8 candidates/block.
// Cross-lane sums use recursive-halving reduce-scatter (15 shuffles per
// 16-value group); the induced bit-reversal permutation is harmless since
// every group feeds a min. Registers capped at 64 -> 32 warps/SM.

#define SET_SIZE 8
#define EMB_DIM  64
#define ROW_BYTES 256
#define FULL 0xffffffffu
#define PAD_BIG 1e30f

__device__ __forceinline__ float dot4(const float4& a, const float4& b) {
    return a.x * b.x + a.y * b.y + a.z * b.z + a.w * b.w;
}

__device__ __forceinline__ float fast_sigmoid(float x) {
    return 1.0f / (1.0f + __expf(-x));
}

__device__ __forceinline__ int clampi(int v, int hi) {
    return min(max(v, 0), hi);
}

__device__ __forceinline__ float4 ldg4_off(const char* base, unsigned byte_off) {
    return __ldg(reinterpret_cast<const float4*>(base + byte_off));
}

// Reduce-scatter 16 values across the 16-lane segment (sub = lane & 15).
// Afterwards each lane holds the full 16-lane sum of value index bitrev4(sub).
__device__ __forceinline__ float rs16(float (&cur)[16], int sub) {
    #pragma unroll
    for (int j = 0; j < 8; j++) {
        float send = (sub & 1) ? cur[j] : cur[j + 8];
        float keep = (sub & 1) ? cur[j + 8] : cur[j];
        cur[j] = keep + __shfl_xor_sync(FULL, send, 1);
    }
    #pragma unroll
    for (int j = 0; j < 4; j++) {
        float send = (sub & 2) ? cur[j] : cur[j + 4];
        float keep = (sub & 2) ? cur[j + 4] : cur[j];
        cur[j] = keep + __shfl_xor_sync(FULL, send, 2);
    }
    #pragma unroll
    for (int j = 0; j < 2; j++) {
        float send = (sub & 4) ? cur[j] : cur[j + 2];
        float keep = (sub & 4) ? cur[j + 2] : cur[j];
        cur[j] = keep + __shfl_xor_sync(FULL, send, 4);
    }
    {
        float send = (sub & 8) ? cur[0] : cur[1];
        float keep = (sub & 8) ? cur[1] : cur[0];
        cur[0] = keep + __shfl_xor_sync(FULL, send, 8);
    }
    return cur[0];
}

__global__ __launch_bounds__(128, 8)
void hyperedge_score_kernel(const float* __restrict__ node_emb,
                            const float* __restrict__ hyper_emb,
                            const int* __restrict__ h,
                            const int* __restrict__ X,
                            float* __restrict__ out,
                            int n_cand, int n_nodes, int n_hyper)
{
    const int lane = threadIdx.x & 31;
    const int warp = threadIdx.x >> 5;
    const int seg  = lane >> 4;   // candidate within warp (0..1)
    const int sub  = lane & 15;   // float4 slice id      (0..15)

    int e = (blockIdx.x * 4 + warp) * 2 + seg;
    const bool valid = (e < n_cand);
    int ec = valid ? e : (n_cand - 1);

    // Index loads (lanes 0..7 and 8..15 of a segment read the same 8 ints).
    int my_idx = clampi(X[ec * SET_SIZE + (sub & 7)], n_nodes - 1);
    int h_idx  = clampi(h[ec], n_hyper - 1);

    const char* nbase = reinterpret_cast<const char*>(node_emb);
    const char* hbase = reinterpret_cast<const char*>(hyper_emb);
    const unsigned lane_off = (unsigned)(sub * 16);   // float4 within row

    // Gather src slice: one float4 (dims [4*sub, 4*sub+4)).
    float4 s = ldg4_off(hbase, (unsigned)h_idx * ROW_BYTES + lane_off);

    // Gather 8 node slices, all loads issued up front (MLP).
    float4 nv[SET_SIZE];
    #pragma unroll
    for (int t = 0; t < SET_SIZE; t++) {
        int idx = __shfl_sync(FULL, my_idx, seg * 16 + t);
        nv[t] = ldg4_off(nbase, (unsigned)idx * ROW_BYTES + lane_off);
    }

    float cur[16];

    // ---- group 0: star (indices 0..7) + diagonal (indices 8..15) ----
    #pragma unroll
    for (int t = 0; t < SET_SIZE; t++) cur[t] = dot4(s, nv[t]);
    #pragma unroll
    for (int t = 0; t < SET_SIZE; t++) cur[8 + t] = dot4(nv[t], nv[t]);

    float v = rs16(cur, sub);
    // bitrev: even lanes hold star sums, odd lanes hold diagonal sums.
    v = fminf(v, __shfl_xor_sync(FULL, v, 2));
    v = fminf(v, __shfl_xor_sync(FULL, v, 4));
    v = fminf(v, __shfl_xor_sync(FULL, v, 8));
    float star_min = v;                               // valid on even lanes
    float diag_min = __shfl_xor_sync(FULL, v, 1);     // odd lanes' min, now on even

    // ---- off-diagonal pairs: 28 dots in 2 chunks of 16 ----
    {
        const int PA0[16] = {0,0,0,0,0,0,0, 1,1,1,1,1,1, 2,2,2};
        const int PB0[16] = {1,2,3,4,5,6,7, 2,3,4,5,6,7, 3,4,5};
        #pragma unroll
        for (int k = 0; k < 16; k++) cur[k] = dot4(nv[PA0[k]], nv[PB0[k]]);
    }
    float p0 = rs16(cur, sub);

    {
        const int PA1[12] = {2,2, 3,3,3,3, 4,4,4, 5,5, 6};
        const int PB1[12] = {6,7, 4,5,6,7, 5,6,7, 6,7, 7};
        #pragma unroll
        for (int k = 0; k < 12; k++) cur[k] = dot4(nv[PA1[k]], nv[PB1[k]]);
        #pragma unroll
        for (int k = 12; k < 16; k++) cur[k] = PAD_BIG;
    }
    float p1 = rs16(cur, sub);

    float pmin = fminf(p0, p1);
    pmin = fminf(pmin, __shfl_xor_sync(FULL, pmin, 1));
    pmin = fminf(pmin, __shfl_xor_sync(FULL, pmin, 2));
    pmin = fminf(pmin, __shfl_xor_sync(FULL, pmin, 4));
    pmin = fminf(pmin, __shfl_xor_sync(FULL, pmin, 8));

    if (valid && sub == 0) {
        float clique = fminf(diag_min, pmin);
        float2 o = make_float2(fast_sigmoid(star_min), fast_sigmoid(clique));
        reinterpret_cast<float2*>(out)[e] = o;
    }
}

extern "C" void kernel_launch(void* const* d_in, const int* in_sizes, int n_in,
                              void* d_out, int out_size) {
    const float* node_emb  = (const float*)d_in[0];
    const float* hyper_emb = (const float*)d_in[1];
    const int*   h         = (const int*)d_in[2];
    const int*   X         = (const int*)d_in[3];
    float*       out       = (float*)d_out;

    const int n_cand  = in_sizes[2];
    const int n_nodes = in_sizes[0] / EMB_DIM;
    const int n_hyper = in_sizes[1] / EMB_DIM;

    const int cands_per_block = 8;    // 4 warps * 2 candidates
    const int blocks = (n_cand + cands_per_block - 1) / cands_per_block;

    hyperedge_score_kernel<<<blocks, 128>>>(node_emb, hyper_emb, h, X, out,
                                            n_cand, n_nodes, n_hyper);
}

// round 6
// speedup vs baseline: 2.0764x; 1.0788x over previous
#include <cuda_runtime.h>
#include <cuda_bf16.h>

// Problem shapes:
//   node_emb      [100000, 64] f32
//   hyperedge_emb [ 50000, 64] f32
//   h             [200000]      i32
//   X             [200000, 8]   i32
//   out           [200000, 2]   f32
//
// Layout: 16 lanes per candidate (lane owns one float4 = 4 dims, held as a
// ulonglong2 so the packed f32x2 pairs come straight out of LDG.128),
// 2 candidates per warp, 128 threads/block.
// Dot products use Blackwell packed f32x2 FMA (2 fp32 ops per issue slot).
// Cross-lane sums use recursive-halving reduce-scatter (15 shuffles per
// 16-value group); the induced bit-reversal permutation is harmless since
// every group feeds a min. Registers capped at 64 -> 32 warps/SM.

#define SET_SIZE 8
#define EMB_DIM  64
#define ROW_BYTES 256
#define FULL 0xffffffffu
#define PAD_BIG 1e30f

typedef unsigned long long u64;

__device__ __forceinline__ u64 mul2(u64 a, u64 b) {
    u64 r;
    asm("mul.rn.f32x2 %0, %1, %2;" : "=l"(r) : "l"(a), "l"(b));
    return r;
}
__device__ __forceinline__ u64 fma2(u64 a, u64 b, u64 c) {
    u64 r;
    asm("fma.rn.f32x2 %0, %1, %2, %3;" : "=l"(r) : "l"(a), "l"(b), "l"(c));
    return r;
}

// dot of two 4-dim slices held as packed f32x2 pairs: 2 packed ops + 1 FADD.
__device__ __forceinline__ float dot4p(const ulonglong2& a, const ulonglong2& b) {
    u64 p = mul2(a.x, b.x);
    p = fma2(a.y, b.y, p);
    float lo = __uint_as_float((unsigned)p);
    float hi = __uint_as_float((unsigned)(p >> 32));
    return lo + hi;
}

__device__ __forceinline__ float fast_sigmoid(float x) {
    return 1.0f / (1.0f + __expf(-x));
}

__device__ __forceinline__ int clampi(int v, int hi) {
    return min(max(v, 0), hi);
}

__device__ __forceinline__ ulonglong2 ldg16_off(const char* base, unsigned byte_off) {
    return __ldg(reinterpret_cast<const ulonglong2*>(base + byte_off));
}

// Reduce-scatter 16 values across the 16-lane segment (sub = lane & 15).
// Afterwards each lane holds the full 16-lane sum of value index bitrev4(sub).
__device__ __forceinline__ float rs16(float (&cur)[16], int sub) {
    #pragma unroll
    for (int j = 0; j < 8; j++) {
        float send = (sub & 1) ? cur[j] : cur[j + 8];
        float keep = (sub & 1) ? cur[j + 8] : cur[j];
        cur[j] = keep + __shfl_xor_sync(FULL, send, 1);
    }
    #pragma unroll
    for (int j = 0; j < 4; j++) {
        float send = (sub & 2) ? cur[j] : cur[j + 4];
        float keep = (sub & 2) ? cur[j + 4] : cur[j];
        cur[j] = keep + __shfl_xor_sync(FULL, send, 2);
    }
    #pragma unroll
    for (int j = 0; j < 2; j++) {
        float send = (sub & 4) ? cur[j] : cur[j + 2];
        float keep = (sub & 4) ? cur[j + 2] : cur[j];
        cur[j] = keep + __shfl_xor_sync(FULL, send, 4);
    }
    {
        float send = (sub & 8) ? cur[0] : cur[1];
        float keep = (sub & 8) ? cur[1] : cur[0];
        cur[0] = keep + __shfl_xor_sync(FULL, send, 8);
    }
    return cur[0];
}

__global__ __launch_bounds__(128, 8)
void hyperedge_score_kernel(const float* __restrict__ node_emb,
                            const float* __restrict__ hyper_emb,
                            const int* __restrict__ h,
                            const int* __restrict__ X,
                            float* __restrict__ out,
                            int n_cand, int n_nodes, int n_hyper)
{
    const int lane = threadIdx.x & 31;
    const int warp = threadIdx.x >> 5;
    const int seg  = lane >> 4;   // candidate within warp (0..1)
    const int sub  = lane & 15;   // float4 slice id      (0..15)

    int e = (blockIdx.x * 4 + warp) * 2 + seg;
    const bool valid = (e < n_cand);
    int ec = valid ? e : (n_cand - 1);

    // Index loads (lanes 0..7 and 8..15 of a segment read the same 8 ints).
    int my_idx = clampi(X[ec * SET_SIZE + (sub & 7)], n_nodes - 1);
    int h_idx  = clampi(h[ec], n_hyper - 1);

    const char* nbase = reinterpret_cast<const char*>(node_emb);
    const char* hbase = reinterpret_cast<const char*>(hyper_emb);
    const unsigned lane_off = (unsigned)(sub * 16);   // float4 within row

    // Gather src slice: one 16B chunk (dims [4*sub, 4*sub+4)).
    ulonglong2 s = ldg16_off(hbase, (unsigned)h_idx * ROW_BYTES + lane_off);

    // Gather 8 node slices, all loads issued up front (MLP).
    ulonglong2 nv[SET_SIZE];
    #pragma unroll
    for (int t = 0; t < SET_SIZE; t++) {
        int idx = __shfl_sync(FULL, my_idx, seg * 16 + t);
        nv[t] = ldg16_off(nbase, (unsigned)idx * ROW_BYTES + lane_off);
    }

    float cur[16];

    // ---- group 0: star (indices 0..7) + diagonal (indices 8..15) ----
    #pragma unroll
    for (int t = 0; t < SET_SIZE; t++) cur[t] = dot4p(s, nv[t]);
    #pragma unroll
    for (int t = 0; t < SET_SIZE; t++) cur[8 + t] = dot4p(nv[t], nv[t]);

    float v = rs16(cur, sub);
    // bitrev: even lanes hold star sums, odd lanes hold diagonal sums.
    v = fminf(v, __shfl_xor_sync(FULL, v, 2));
    v = fminf(v, __shfl_xor_sync(FULL, v, 4));
    v = fminf(v, __shfl_xor_sync(FULL, v, 8));
    float star_min = v;                               // valid on even lanes
    float diag_min = __shfl_xor_sync(FULL, v, 1);     // odd lanes' min, now on even

    // ---- off-diagonal pairs: 28 dots in 2 chunks of 16 ----
    {
        const int PA0[16] = {0,0,0,0,0,0,0, 1,1,1,1,1,1, 2,2,2};
        const int PB0[16] = {1,2,3,4,5,6,7, 2,3,4,5,6,7, 3,4,5};
        #pragma unroll
        for (int k = 0; k < 16; k++) cur[k] = dot4p(nv[PA0[k]], nv[PB0[k]]);
    }
    float p0 = rs16(cur, sub);

    {
        const int PA1[12] = {2,2, 3,3,3,3, 4,4,4, 5,5, 6};
        const int PB1[12] = {6,7, 4,5,6,7, 5,6,7, 6,7, 7};
        #pragma unroll
        for (int k = 0; k < 12; k++) cur[k] = dot4p(nv[PA1[k]], nv[PB1[k]]);
        #pragma unroll
        for (int k = 12; k < 16; k++) cur[k] = PAD_BIG;
    }
    float p1 = rs16(cur, sub);

    float pmin = fminf(p0, p1);
    pmin = fminf(pmin, __shfl_xor_sync(FULL, pmin, 1));
    pmin = fminf(pmin, __shfl_xor_sync(FULL, pmin, 2));
    pmin = fminf(pmin, __shfl_xor_sync(FULL, pmin, 4));
    pmin = fminf(pmin, __shfl_xor_sync(FULL, pmin, 8));

    if (valid && sub == 0) {
        float clique = fminf(diag_min, pmin);
        float2 o = make_float2(fast_sigmoid(star_min), fast_sigmoid(clique));
        reinterpret_cast<float2*>(out)[e] = o;
    }
}

extern "C" void kernel_launch(void* const* d_in, const int* in_sizes, int n_in,
                              void* d_out, int out_size) {
    const float* node_emb  = (const float*)d_in[0];
    const float* hyper_emb = (const float*)d_in[1];
    const int*   h         = (const int*)d_in[2];
    const int*   X         = (const int*)d_in[3];
    float*       out       = (float*)d_out;

    const int n_cand  = in_sizes[2];
    const int n_nodes = in_sizes[0] / EMB_DIM;
    const int n_hyper = in_sizes[1] / EMB_DIM;

    const int cands_per_block = 8;    // 4 warps * 2 candidates
    const int blocks = (n_cand + cands_per_block - 1) / cands_per_block;

    hyperedge_score_kernel<<<blocks, 128>>>(node_emb, hyper_emb, h, X, out,
                                            n_cand, n_nodes, n_hyper);
}

// round 7
// speedup vs baseline: 2.1548x; 1.0378x over previous
#include <cuda_runtime.h>
#include <cuda_bf16.h>

// Problem shapes:
//   node_emb      [100000, 64] f32
//   hyperedge_emb [ 50000, 64] f32
//   h             [200000]      i32
//   X             [200000, 8]   i32
//   out           [200000, 2]   f32
//
// Layout: 16 lanes per candidate (lane owns one float4 = 4 dims, held as a
// ulonglong2 so packed f32x2 pairs come straight out of LDG.128),
// 2 candidates per warp, 128 threads/block.
// Dot products use Blackwell packed f32x2 FMA. Cross-lane sums use
// recursive-halving reduce-scatter (15 shuffles / 16-value group); the
// induced bit-reversal permutation is harmless since every group feeds a
// min. Each lane loads its candidate's full X row (2x int4, uniform within
// the 16-lane segment -> L1 broadcast) instead of shuffle-broadcasting
// indices. Registers capped at 64 -> 32 warps/SM.

#define SET_SIZE 8
#define EMB_DIM  64
#define ROW_BYTES 256
#define FULL 0xffffffffu
#define PAD_BIG 1e30f

typedef unsigned long long u64;

__device__ __forceinline__ u64 mul2(u64 a, u64 b) {
    u64 r;
    asm("mul.rn.f32x2 %0, %1, %2;" : "=l"(r) : "l"(a), "l"(b));
    return r;
}
__device__ __forceinline__ u64 fma2(u64 a, u64 b, u64 c) {
    u64 r;
    asm("fma.rn.f32x2 %0, %1, %2, %3;" : "=l"(r) : "l"(a), "l"(b), "l"(c));
    return r;
}

// dot of two 4-dim slices held as packed f32x2 pairs: 2 packed ops + 1 FADD.
__device__ __forceinline__ float dot4p(const ulonglong2& a, const ulonglong2& b) {
    u64 p = mul2(a.x, b.x);
    p = fma2(a.y, b.y, p);
    float lo = __uint_as_float((unsigned)p);
    float hi = __uint_as_float((unsigned)(p >> 32));
    return lo + hi;
}

__device__ __forceinline__ float fast_sigmoid(float x) {
    return 1.0f / (1.0f + __expf(-x));
}

__device__ __forceinline__ ulonglong2 ldg16_off(const char* base, unsigned byte_off) {
    return __ldg(reinterpret_cast<const ulonglong2*>(base + byte_off));
}

// Reduce-scatter 16 values across the 16-lane segment (sub = lane & 15).
// Afterwards each lane holds the full 16-lane sum of value index bitrev4(sub).
__device__ __forceinline__ float rs16(float (&cur)[16], int sub) {
    #pragma unroll
    for (int j = 0; j < 8; j++) {
        float send = (sub & 1) ? cur[j] : cur[j + 8];
        float keep = (sub & 1) ? cur[j + 8] : cur[j];
        cur[j] = keep + __shfl_xor_sync(FULL, send, 1);
    }
    #pragma unroll
    for (int j = 0; j < 4; j++) {
        float send = (sub & 2) ? cur[j] : cur[j + 4];
        float keep = (sub & 2) ? cur[j + 4] : cur[j];
        cur[j] = keep + __shfl_xor_sync(FULL, send, 2);
    }
    #pragma unroll
    for (int j = 0; j < 2; j++) {
        float send = (sub & 4) ? cur[j] : cur[j + 2];
        float keep = (sub & 4) ? cur[j + 2] : cur[j];
        cur[j] = keep + __shfl_xor_sync(FULL, send, 4);
    }
    {
        float send = (sub & 8) ? cur[0] : cur[1];
        float keep = (sub & 8) ? cur[1] : cur[0];
        cur[0] = keep + __shfl_xor_sync(FULL, send, 8);
    }
    return cur[0];
}

__global__ __launch_bounds__(128, 8)
void hyperedge_score_kernel(const float* __restrict__ node_emb,
                            const float* __restrict__ hyper_emb,
                            const int* __restrict__ h,
                            const int* __restrict__ X,
                            float* __restrict__ out,
                            int n_cand)
{
    const int lane = threadIdx.x & 31;
    const int warp = threadIdx.x >> 5;
    const int seg  = lane >> 4;   // candidate within warp (0..1)
    const int sub  = lane & 15;   // float4 slice id      (0..15)

    int e = (blockIdx.x * 4 + warp) * 2 + seg;
    int ec = min(e, n_cand - 1);

    // Each lane loads its candidate's full X row: 2x int4, uniform within
    // the 16-lane segment (L1 broadcast). Removes 8 idx shuffles + chain.
    const int4* xrow = reinterpret_cast<const int4*>(X + ec * SET_SIZE);
    int4 xa = __ldg(xrow);
    int4 xb = __ldg(xrow + 1);
    int h_idx = __ldg(h + ec);

    const char* nbase = reinterpret_cast<const char*>(node_emb);
    const char* hbase = reinterpret_cast<const char*>(hyper_emb);
    const unsigned lane_off = (unsigned)(sub * 16);   // float4 within row

    // Gather src slice + 8 node slices; all loads issued up front (MLP).
    ulonglong2 s = ldg16_off(hbase, (unsigned)h_idx * ROW_BYTES + lane_off);

    ulonglong2 nv[SET_SIZE];
    nv[0] = ldg16_off(nbase, (unsigned)xa.x * ROW_BYTES + lane_off);
    nv[1] = ldg16_off(nbase, (unsigned)xa.y * ROW_BYTES + lane_off);
    nv[2] = ldg16_off(nbase, (unsigned)xa.z * ROW_BYTES + lane_off);
    nv[3] = ldg16_off(nbase, (unsigned)xa.w * ROW_BYTES + lane_off);
    nv[4] = ldg16_off(nbase, (unsigned)xb.x * ROW_BYTES + lane_off);
    nv[5] = ldg16_off(nbase, (unsigned)xb.y * ROW_BYTES + lane_off);
    nv[6] = ldg16_off(nbase, (unsigned)xb.z * ROW_BYTES + lane_off);
    nv[7] = ldg16_off(nbase, (unsigned)xb.w * ROW_BYTES + lane_off);

    float cur[16];

    // ---- group 0: star (indices 0..7) + diagonal (indices 8..15) ----
    #pragma unroll
    for (int t = 0; t < SET_SIZE; t++) cur[t] = dot4p(s, nv[t]);
    #pragma unroll
    for (int t = 0; t < SET_SIZE; t++) cur[8 + t] = dot4p(nv[t], nv[t]);

    float v = rs16(cur, sub);
    // bitrev: even lanes hold star sums, odd lanes hold diagonal sums.
    v = fminf(v, __shfl_xor_sync(FULL, v, 2));
    v = fminf(v, __shfl_xor_sync(FULL, v, 4));
    v = fminf(v, __shfl_xor_sync(FULL, v, 8));
    float star_min = v;                               // valid on even lanes
    float diag_min = __shfl_xor_sync(FULL, v, 1);     // odd lanes' min, now on even

    // ---- off-diagonal pairs: 28 dots in 2 chunks of 16 ----
    {
        const int PA0[16] = {0,0,0,0,0,0,0, 1,1,1,1,1,1, 2,2,2};
        const int PB0[16] = {1,2,3,4,5,6,7, 2,3,4,5,6,7, 3,4,5};
        #pragma unroll
        for (int k = 0; k < 16; k++) cur[k] = dot4p(nv[PA0[k]], nv[PB0[k]]);
    }
    float p0 = rs16(cur, sub);

    {
        const int PA1[12] = {2,2, 3,3,3,3, 4,4,4, 5,5, 6};
        const int PB1[12] = {6,7, 4,5,6,7, 5,6,7, 6,7, 7};
        #pragma unroll
        for (int k = 0; k < 12; k++) cur[k] = dot4p(nv[PA1[k]], nv[PB1[k]]);
        #pragma unroll
        for (int k = 12; k < 16; k++) cur[k] = PAD_BIG;
    }
    float p1 = rs16(cur, sub);

    float pmin = fminf(p0, p1);
    pmin = fminf(pmin, __shfl_xor_sync(FULL, pmin, 1));
    pmin = fminf(pmin, __shfl_xor_sync(FULL, pmin, 2));
    pmin = fminf(pmin, __shfl_xor_sync(FULL, pmin, 4));
    pmin = fminf(pmin, __shfl_xor_sync(FULL, pmin, 8));

    if (e < n_cand && sub == 0) {
        float clique = fminf(diag_min, pmin);
        float2 o = make_float2(fast_sigmoid(star_min), fast_sigmoid(clique));
        reinterpret_cast<float2*>(out)[e] = o;
    }
}

extern "C" void kernel_launch(void* const* d_in, const int* in_sizes, int n_in,
                              void* d_out, int out_size) {
    const float* node_emb  = (const float*)d_in[0];
    const float* hyper_emb = (const float*)d_in[1];
    const int*   h         = (const int*)d_in[2];
    const int*   X         = (const int*)d_in[3];
    float*       out       = (float*)d_out;

    const int n_cand = in_sizes[2];

    const int cands_per_block = 8;    // 4 warps * 2 candidates
    const int blocks = (n_cand + cands_per_block - 1) / cands_per_block;

    hyperedge_score_kernel<<<blocks, 128>>>(node_emb, hyper_emb, h, X, out, n_cand);
}